// round 2
// baseline (speedup 1.0000x reference)
#include <cuda_runtime.h>
#include <math.h>

// Problem constants (from reference): N=100000, D=256, E=3200000
#define NMAX 100000

// Scratch (device globals — allocation-free rule)
__device__ float g_diag[NMAX];
__device__ float g_deg[NMAX];

// ---------------------------------------------------------------------------
// K0: zero the degree array (must run every call — graph replays)
// ---------------------------------------------------------------------------
__global__ void k_zero(int n) {
    int i = blockIdx.x * blockDim.x + threadIdx.x;
    if (i < n) g_deg[i] = 0.0f;
}

// ---------------------------------------------------------------------------
// K1: diag[i] = sigmoid(dot(x[i,:], w) + b)   (warp per row, D=256 fixed)
// ---------------------------------------------------------------------------
__global__ void k_diag(const float* __restrict__ x,
                       const float* __restrict__ w,
                       const float* __restrict__ b,
                       int n) {
    __shared__ float4 ws[64];
    int t = threadIdx.x;
    if (t < 64) ws[t] = ((const float4*)w)[t];
    __syncthreads();

    int lane = t & 31;
    int row = blockIdx.x * (blockDim.x >> 5) + (t >> 5);
    if (row >= n) return;

    const float4* xr = (const float4*)(x + (size_t)row * 256);
    float4 a0 = xr[lane];
    float4 a1 = xr[lane + 32];
    float4 w0 = ws[lane];
    float4 w1 = ws[lane + 32];
    float s = a0.x * w0.x + a0.y * w0.y + a0.z * w0.z + a0.w * w0.w
            + a1.x * w1.x + a1.y * w1.y + a1.z * w1.z + a1.w * w1.w;
#pragma unroll
    for (int o = 16; o; o >>= 1) s += __shfl_xor_sync(0xffffffffu, s, o);
    if (lane == 0) {
        float z = s + b[0];
        g_diag[row] = 1.0f / (1.0f + expf(-z));
    }
}

// ---------------------------------------------------------------------------
// K2: degree accumulation + (optionally) write edge_index copy to output.
//     edge_index is INT32 (jax default x64-disabled): rows at [0,E), cols [E,2E)
// ---------------------------------------------------------------------------
__global__ void k_deg_copy(const int* __restrict__ ei,
                           float* __restrict__ out_idx,
                           int E, int write_idx) {
    int e = blockIdx.x * blockDim.x + threadIdx.x;
    if (e >= E) return;
    int c = ei[E + e];
    if (write_idx) {
        out_idx[e]     = (float)ei[e];
        out_idx[E + e] = (float)c;
    }
    if ((unsigned)c < (unsigned)NMAX)
        atomicAdd(&g_deg[c], 1.0f);
}

// ---------------------------------------------------------------------------
// K3: deg -> 1/deg   (zero-degree -> inf, matching torch pow(-1))
// ---------------------------------------------------------------------------
__global__ void k_inv(int n) {
    int i = blockIdx.x * blockDim.x + threadIdx.x;
    if (i < n) g_deg[i] = 1.0f / g_deg[i];
}

// ---------------------------------------------------------------------------
// K4: per-edge value: val = deg_inv[row] * attr[e] * diag[col]
// ---------------------------------------------------------------------------
__global__ void k_val(const int* __restrict__ ei,
                      const float* __restrict__ attr,
                      float* __restrict__ outv,
                      int E) {
    int e = blockIdx.x * blockDim.x + threadIdx.x;
    if (e >= E) return;
    unsigned r = (unsigned)ei[e];
    unsigned c = (unsigned)ei[E + e];
    float di = (r < NMAX) ? g_deg[r]  : 0.0f;
    float dg = (c < NMAX) ? g_diag[c] : 0.0f;
    outv[e] = di * attr[e] * dg;
}

// ---------------------------------------------------------------------------
extern "C" void kernel_launch(void* const* d_in, const int* in_sizes, int n_in,
                              void* d_out, int out_size) {
    const float* x    = (const float*)d_in[0];
    const int*   ei   = (const int*)d_in[1];     // int32 (2, E)
    const float* attr = (const float*)d_in[2];
    const float* w    = (const float*)d_in[3];
    const float* b    = (const float*)d_in[4];

    const int E  = in_sizes[2];          // edge count
    const int Dd = in_sizes[3];          // feature dim (256)
    const int n  = in_sizes[0] / Dd;     // node count

    float* out = (float*)d_out;
    float* out_vals;
    int write_idx;
    if (out_size >= 3 * E) {             // [edge_index(2E) | vals(E)] as float32
        write_idx = 1;
        out_vals = out + 2 * (size_t)E;
    } else {                             // vals only
        write_idx = 0;
        out_vals = out;
    }

    const int T = 256;

    k_zero<<<(n + T - 1) / T, T>>>(n);
    k_diag<<<(n + 7) / 8, T>>>(x, w, b, n);
    k_deg_copy<<<(E + T - 1) / T, T>>>(ei, out, E, write_idx);
    k_inv<<<(n + T - 1) / T, T>>>(n);
    k_val<<<(E + T - 1) / T, T>>>(ei, attr, out_vals, E);
}